// round 1
// baseline (speedup 1.0000x reference)
#include <cuda_runtime.h>

#define DIM     512
#define D_INNER 1024
#define DT_RANK 32
#define D_STATE 16
#define B_SZ    4
#define N_TOK   4097

// ---------------- scratch (device globals, allocation-free) ----------------
__device__ __align__(16) float g_q    [B_SZ * DIM];
__device__ __align__(16) float g_xs   [B_SZ * D_INNER];
__device__ __align__(16) float g_sz   [B_SZ * D_INNER];
__device__ __align__(16) float g_y    [B_SZ * D_INNER];
__device__ __align__(16) float g_mixed[B_SZ * DIM];

// ---------------- helpers ----------------
__device__ __forceinline__ float siluf(float x) {
    return x / (1.0f + __expf(-x));
}
__device__ __forceinline__ float softplusf(float x) {
    return (x > 20.0f) ? x : log1pf(__expf(x));
}

// Warp-collective dot product of two length-(N4*4) float vectors (float4 reads).
template <int N4>
__device__ __forceinline__ float warp_dot(const float4* __restrict__ v4,
                                          const float4* __restrict__ w4) {
    int lane = threadIdx.x & 31;
    float s = 0.0f;
#pragma unroll
    for (int i = 0; i < N4 / 32; i++) {
        float4 a = v4[lane + i * 32];
        float4 b = w4[lane + i * 32];
        s += a.x * b.x + a.y * b.y + a.z * b.z + a.w * b.w;
    }
#pragma unroll
    for (int off = 16; off; off >>= 1)
        s += __shfl_xor_sync(0xffffffffu, s, off);
    return s;
}

// ---------------- K0: bulk copy of patch tokens (dst idx == src idx) -------
__global__ void k_copy(const float4* __restrict__ x4, float4* __restrict__ o4) {
    const int per_batch = 4096 * DIM / 4;           // 524288 float4 per batch
    const int batch_stride = N_TOK * DIM / 4;       // 524416
    const int total = B_SZ * per_batch;             // 2097152
    for (int i = blockIdx.x * blockDim.x + threadIdx.x; i < total;
         i += gridDim.x * blockDim.x) {
        int b   = i / per_batch;
        int off = i - b * per_batch;
        int idx = b * batch_stride + (DIM / 4) + off;  // skip cls token
        o4[idx] = x4[idx];
    }
}

// ---------------- K1: q = cls @ q_w.T ----------------
__global__ void k_q(const float* __restrict__ x, const float* __restrict__ q_w) {
    int warp = (blockIdx.x * blockDim.x + threadIdx.x) >> 5;
    if (warp >= B_SZ * DIM) return;
    int b = warp / DIM, r = warp % DIM;
    const float4* v4 = (const float4*)(x + (size_t)b * N_TOK * DIM);  // cls token
    const float4* w4 = (const float4*)(q_w + (size_t)r * DIM);
    float s = warp_dot<DIM / 4>(v4, w4);
    if ((threadIdx.x & 31) == 0) g_q[b * DIM + r] = s;
}

// ---------------- K2: xz = q @ in_proj_w.T ; fused conv-tap + silu ---------
__global__ void k_xz(const float* __restrict__ in_proj_w,
                     const float* __restrict__ conv_w,
                     const float* __restrict__ conv_b) {
    int warp = (blockIdx.x * blockDim.x + threadIdx.x) >> 5;
    if (warp >= B_SZ * 2 * D_INNER) return;
    int b = warp / (2 * D_INNER), j = warp % (2 * D_INNER);
    const float4* v4 = (const float4*)(g_q + b * DIM);
    const float4* w4 = (const float4*)(in_proj_w + (size_t)j * DIM);
    float s = warp_dot<DIM / 4>(v4, w4);
    if ((threadIdx.x & 31) == 0) {
        if (j < D_INNER) {
            // causal conv at t=0: only last tap contributes
            float t = s * conv_w[j * 4 + 3] + conv_b[j];
            g_xs[b * D_INNER + j] = siluf(t);
        } else {
            g_sz[b * D_INNER + (j - D_INNER)] = siluf(s);
        }
    }
}

// ---------------- K3: x_dbl, delta, first-step scan, gating (fused) --------
// One block per batch, 1024 threads.
__global__ void k_scan(const float* __restrict__ x_proj_w,
                       const float* __restrict__ dt_w,
                       const float* __restrict__ dt_b,
                       const float* __restrict__ Dv) {
    __shared__ __align__(16) float s_xs[D_INNER];
    __shared__ float s_db[DT_RANK + 2 * D_STATE];  // 64

    int b = blockIdx.x, t = threadIdx.x;
    s_xs[t] = g_xs[b * D_INNER + t];
    __syncthreads();

    int warp = t >> 5;
    // 32 warps, 64 rows of x_proj -> 2 rows per warp
#pragma unroll
    for (int rr = 0; rr < 2; rr++) {
        int r = warp * 2 + rr;
        float s = warp_dot<D_INNER / 4>((const float4*)s_xs,
                                        (const float4*)(x_proj_w + (size_t)r * D_INNER));
        if ((t & 31) == 0) s_db[r] = s;
    }
    __syncthreads();

    // per-thread d = t
    float dtv = dt_b[t];
#pragma unroll
    for (int k = 0; k < DT_RANK; k++) dtv += s_db[k] * dt_w[t * DT_RANK + k];
    float delta = softplusf(dtv);

    float bc = 0.0f;
#pragma unroll
    for (int n = 0; n < D_STATE; n++)
        bc += s_db[DT_RANK + n] * s_db[DT_RANK + D_STATE + n];

    float u = s_xs[t];
    // h0 = 0  =>  y = delta*u*(B·C) + u*D ; then gate by silu(z)
    float y = (delta * u * bc + u * Dv[t]) * g_sz[b * D_INNER + t];
    g_y[b * D_INNER + t] = y;
}

// ---------------- K4: mixed = y @ out_proj_w.T ----------------
__global__ void k_mixed(const float* __restrict__ out_proj_w) {
    int warp = (blockIdx.x * blockDim.x + threadIdx.x) >> 5;
    if (warp >= B_SZ * DIM) return;
    int b = warp / DIM, r = warp % DIM;
    const float4* v4 = (const float4*)(g_y + b * D_INNER);
    const float4* w4 = (const float4*)(out_proj_w + (size_t)r * D_INNER);
    float s = warp_dot<D_INNER / 4>(v4, w4);
    if ((threadIdx.x & 31) == 0) g_mixed[b * DIM + r] = s;
}

// ---------------- K5: upd_cls = mixed @ proj_w.T + proj_b -> out[:,0,:] ----
__global__ void k_out(const float* __restrict__ proj_w,
                      const float* __restrict__ proj_b,
                      float* __restrict__ out) {
    int warp = (blockIdx.x * blockDim.x + threadIdx.x) >> 5;
    if (warp >= B_SZ * DIM) return;
    int b = warp / DIM, r = warp % DIM;
    const float4* v4 = (const float4*)(g_mixed + b * DIM);
    const float4* w4 = (const float4*)(proj_w + (size_t)r * DIM);
    float s = warp_dot<DIM / 4>(v4, w4);
    if ((threadIdx.x & 31) == 0)
        out[(size_t)b * N_TOK * DIM + r] = s + proj_b[r];
}

// ---------------- launch ----------------
extern "C" void kernel_launch(void* const* d_in, const int* in_sizes, int n_in,
                              void* d_out, int out_size) {
    const float* x         = (const float*)d_in[0];
    const float* q_w       = (const float*)d_in[1];
    const float* in_proj_w = (const float*)d_in[2];
    const float* conv_w    = (const float*)d_in[3];
    const float* conv_b    = (const float*)d_in[4];
    const float* x_proj_w  = (const float*)d_in[5];
    const float* dt_w      = (const float*)d_in[6];
    const float* dt_b      = (const float*)d_in[7];
    // d_in[8] = A_log (unused: h0 = 0 at first scan step)
    const float* Dv        = (const float*)d_in[9];
    const float* out_proj_w= (const float*)d_in[10];
    const float* proj_w    = (const float*)d_in[11];
    const float* proj_b    = (const float*)d_in[12];
    float* out = (float*)d_out;

    // Bulk patch copy (HBM-bound, dominates runtime)
    k_copy<<<2048, 256>>>((const float4*)x, (float4*)out);

    // CLS-token compute chain (tiny)
    k_q    <<<(B_SZ * DIM) / 8, 256>>>(x, q_w);
    k_xz   <<<(B_SZ * 2 * D_INNER) / 8, 256>>>(in_proj_w, conv_w, conv_b);
    k_scan <<<B_SZ, D_INNER>>>(x_proj_w, dt_w, dt_b, Dv);
    k_mixed<<<(B_SZ * DIM) / 8, 256>>>(out_proj_w);
    k_out  <<<(B_SZ * DIM) / 8, 256>>>(proj_w, proj_b, out);
}

// round 2
// speedup vs baseline: 1.5384x; 1.5384x over previous
#include <cuda_runtime.h>

#define DIM     512
#define D_INNER 1024
#define DT_RANK 32
#define D_STATE 16
#define B_SZ    4
#define N_TOK   4097

// ---------------- scratch (device globals, allocation-free) ----------------
__device__ __align__(16) float g_q    [B_SZ * DIM];
__device__ __align__(16) float g_xs   [B_SZ * D_INNER];
__device__ __align__(16) float g_sz   [B_SZ * D_INNER];
__device__ __align__(16) float g_y    [B_SZ * D_INNER];
__device__ __align__(16) float g_mixed[B_SZ * DIM];

// ---------------- helpers ----------------
__device__ __forceinline__ float siluf(float x) {
    return x / (1.0f + __expf(-x));
}
__device__ __forceinline__ float softplusf(float x) {
    return (x > 20.0f) ? x : log1pf(__expf(x));
}

// Warp-collective dot product of two length-(N4*4) float vectors (float4 reads).
template <int N4>
__device__ __forceinline__ float warp_dot(const float4* __restrict__ v4,
                                          const float4* __restrict__ w4) {
    int lane = threadIdx.x & 31;
    float s = 0.0f;
#pragma unroll
    for (int i = 0; i < N4 / 32; i++) {
        float4 a = v4[lane + i * 32];
        float4 b = w4[lane + i * 32];
        s += a.x * b.x + a.y * b.y + a.z * b.z + a.w * b.w;
    }
#pragma unroll
    for (int off = 16; off; off >>= 1)
        s += __shfl_xor_sync(0xffffffffu, s, off);
    return s;
}

// ---------------- K0: bulk patch copy + q = cls @ q_w.T (independent work) -
// Blocks [0,256): q matvec (2048 warps). Blocks [256, 256+2048): copy.
#define Q_BLOCKS    256
#define COPY_BLOCKS 2048
__global__ void k_copy_q(const float4* __restrict__ x4,
                         const float*  __restrict__ q_w,
                         float4* __restrict__ o4) {
    if (blockIdx.x < Q_BLOCKS) {
        int warp = (blockIdx.x * blockDim.x + threadIdx.x) >> 5;   // 0..2047
        int b = warp / DIM, r = warp % DIM;
        const float4* v4 = x4 + (size_t)b * (N_TOK * DIM / 4);     // cls token
        const float4* w4 = (const float4*)(q_w + (size_t)r * DIM);
        float s = warp_dot<DIM / 4>(v4, w4);
        if ((threadIdx.x & 31) == 0) g_q[b * DIM + r] = s;
        return;
    }
    const int per_batch = 4096 * DIM / 4;           // 524288 float4 per batch
    const int batch_stride = N_TOK * DIM / 4;       // 524416
    const int total = B_SZ * per_batch;             // 2097152
    int tid = (blockIdx.x - Q_BLOCKS) * blockDim.x + threadIdx.x;
    for (int i = tid; i < total; i += COPY_BLOCKS * blockDim.x) {
        int b   = i / per_batch;
        int off = i - b * per_batch;
        int idx = b * batch_stride + (DIM / 4) + off;  // skip cls token
        o4[idx] = x4[idx];
    }
}

// ---------------- K2: xz = q @ in_proj_w.T ; fused conv-tap + silu ---------
__global__ void k_xz(const float* __restrict__ in_proj_w,
                     const float* __restrict__ conv_w,
                     const float* __restrict__ conv_b) {
    int warp = (blockIdx.x * blockDim.x + threadIdx.x) >> 5;
    if (warp >= B_SZ * 2 * D_INNER) return;
    int b = warp / (2 * D_INNER), j = warp % (2 * D_INNER);
    const float4* v4 = (const float4*)(g_q + b * DIM);
    const float4* w4 = (const float4*)(in_proj_w + (size_t)j * DIM);
    float s = warp_dot<DIM / 4>(v4, w4);
    if ((threadIdx.x & 31) == 0) {
        if (j < D_INNER) {
            // causal conv at t=0: only last tap contributes
            float t = s * conv_w[j * 4 + 3] + conv_b[j];
            g_xs[b * D_INNER + j] = siluf(t);
        } else {
            g_sz[b * D_INNER + (j - D_INNER)] = siluf(s);
        }
    }
}

// ---------------- K3: x_dbl, delta, first-step scan, gating (fused) --------
// One block per batch, 1024 threads.
__global__ void k_scan(const float* __restrict__ x_proj_w,
                       const float* __restrict__ dt_w,
                       const float* __restrict__ dt_b,
                       const float* __restrict__ Dv) {
    __shared__ __align__(16) float s_xs[D_INNER];
    __shared__ float s_db[DT_RANK + 2 * D_STATE];  // 64

    int b = blockIdx.x, t = threadIdx.x;
    int lane = t & 31, w = t >> 5;
    s_xs[t] = g_xs[b * D_INNER + t];
    __syncthreads();

    // 32 warps, 64 rows of x_proj -> 2 rows per warp (coalesced float4 reads)
#pragma unroll
    for (int rr = 0; rr < 2; rr++) {
        int r = w * 2 + rr;
        float s = warp_dot<D_INNER / 4>((const float4*)s_xs,
                                        (const float4*)(x_proj_w + (size_t)r * D_INNER));
        if (lane == 0) s_db[r] = s;
    }
    __syncthreads();

    // delta = softplus(dt @ dt_w.T + dt_b), computed warp-cooperatively:
    // warp w handles rows r = w*32 + rr. Row load dt_w[r*32+lane] touches
    // exactly ONE 128B line per warp (coalesced), vs 32 lines/load before.
    float coef = s_db[lane];   // dt coefficient k = lane (lane < 32 == DT_RANK)
    float dtv = 0.0f;
#pragma unroll
    for (int rr = 0; rr < 32; rr++) {
        int r = w * 32 + rr;
        float v = dt_w[r * DT_RANK + lane] * coef;
#pragma unroll
        for (int off = 16; off; off >>= 1)
            v += __shfl_xor_sync(0xffffffffu, v, off);
        if (lane == rr) dtv = v;   // thread t = w*32+rr owns row t
    }
    float delta = softplusf(dtv + dt_b[t]);

    float bc = 0.0f;
#pragma unroll
    for (int n = 0; n < D_STATE; n++)
        bc += s_db[DT_RANK + n] * s_db[DT_RANK + D_STATE + n];

    float u = s_xs[t];
    // h0 = 0  =>  y = delta*u*(B·C) + u*D ; then gate by silu(z)
    float y = (delta * u * bc + u * Dv[t]) * g_sz[b * D_INNER + t];
    g_y[b * D_INNER + t] = y;
}

// ---------------- K4: mixed = y @ out_proj_w.T ----------------
__global__ void k_mixed(const float* __restrict__ out_proj_w) {
    int warp = (blockIdx.x * blockDim.x + threadIdx.x) >> 5;
    if (warp >= B_SZ * DIM) return;
    int b = warp / DIM, r = warp % DIM;
    const float4* v4 = (const float4*)(g_y + b * D_INNER);
    const float4* w4 = (const float4*)(out_proj_w + (size_t)r * D_INNER);
    float s = warp_dot<D_INNER / 4>(v4, w4);
    if ((threadIdx.x & 31) == 0) g_mixed[b * DIM + r] = s;
}

// ---------------- K5: upd_cls = mixed @ proj_w.T + proj_b -> out[:,0,:] ----
__global__ void k_out(const float* __restrict__ proj_w,
                      const float* __restrict__ proj_b,
                      float* __restrict__ out) {
    int warp = (blockIdx.x * blockDim.x + threadIdx.x) >> 5;
    if (warp >= B_SZ * DIM) return;
    int b = warp / DIM, r = warp % DIM;
    const float4* v4 = (const float4*)(g_mixed + b * DIM);
    const float4* w4 = (const float4*)(proj_w + (size_t)r * DIM);
    float s = warp_dot<DIM / 4>(v4, w4);
    if ((threadIdx.x & 31) == 0)
        out[(size_t)b * N_TOK * DIM + r] = s + proj_b[r];
}

// ---------------- launch ----------------
extern "C" void kernel_launch(void* const* d_in, const int* in_sizes, int n_in,
                              void* d_out, int out_size) {
    const float* x         = (const float*)d_in[0];
    const float* q_w       = (const float*)d_in[1];
    const float* in_proj_w = (const float*)d_in[2];
    const float* conv_w    = (const float*)d_in[3];
    const float* conv_b    = (const float*)d_in[4];
    const float* x_proj_w  = (const float*)d_in[5];
    const float* dt_w      = (const float*)d_in[6];
    const float* dt_b      = (const float*)d_in[7];
    // d_in[8] = A_log (unused: h0 = 0 at first scan step)
    const float* Dv        = (const float*)d_in[9];
    const float* out_proj_w= (const float*)d_in[10];
    const float* proj_w    = (const float*)d_in[11];
    const float* proj_b    = (const float*)d_in[12];
    float* out = (float*)d_out;

    // Bulk patch copy (HBM-bound) + q matvec fused (both depend only on x)
    k_copy_q<<<Q_BLOCKS + COPY_BLOCKS, 256>>>((const float4*)x, q_w, (float4*)out);

    // CLS-token compute chain (tiny)
    k_xz   <<<(B_SZ * 2 * D_INNER) / 8, 256>>>(in_proj_w, conv_w, conv_b);
    k_scan <<<B_SZ, D_INNER>>>(x_proj_w, dt_w, dt_b, Dv);
    k_mixed<<<(B_SZ * DIM) / 8, 256>>>(out_proj_w);
    k_out  <<<(B_SZ * DIM) / 8, 256>>>(proj_w, proj_b, out);
}